// round 1
// baseline (speedup 1.0000x reference)
#include <cuda_runtime.h>

// Problem constants (B=2, H=8, S=2048, Sm=2047, D=64)
#define B_   2
#define H_   8
#define S_   2048
#define SM_  2047
#define D_   64
#define BH_  16          // B*H

__device__ __forceinline__ float neg_big() { return -1e9f; }
#define INV_T 0.125f     // 1/TEMPERATURE (= 1/8)

// Output layout (floats), tuple order:
// poi_output, time_output, distance_output, attn1, attn2, attn3
#define O_POI   ((size_t)0)
#define O_TIME  ((size_t)2097152)     // + 16*2048*64
#define O_DIST  ((size_t)4193280)     // + 16*2047*64
#define O_A1    ((size_t)6289408)     // + 16*2047*64
#define O_A2    ((size_t)73398272)    // + 16*2048*2048
#define O_A3    ((size_t)140441616)   // + 16*2047*2047

// ---------------------------------------------------------------------------
// Kernel A: masked scaled scores  S = (Q @ K^T) / T  (mask on stream 0)
// 128x128 output tile per block, 256 threads, 8x8 micro-tile, D=64 fully
// resident in shared memory (stored d-major for conflict-free vector reads).
// ---------------------------------------------------------------------------
__global__ __launch_bounds__(256) void scores_kernel(
    const float* __restrict__ pq, const float* __restrict__ pk,
    const float* __restrict__ tq, const float* __restrict__ tk,
    const float* __restrict__ dq, const float* __restrict__ dk,
    const int*   __restrict__ mask, float* __restrict__ out)
{
    __shared__ __align__(16) float Qs[64][132];
    __shared__ __align__(16) float Ks[64][132];

    const int z      = blockIdx.z;
    const int stream = z >> 4;
    const int bh     = z & 15;

    const float *Q, *K;
    float* A;
    int Sq, Sk;
    const int* M = nullptr;

    if (stream == 0) {
        Sq = S_; Sk = S_;
        Q = pq + (size_t)bh * S_ * D_;
        K = pk + (size_t)bh * S_ * D_;
        A = out + O_A1 + (size_t)bh * S_ * S_;
        M = mask + (size_t)(bh >> 3) * S_ * S_;   // b = bh / H
    } else if (stream == 1) {
        Sq = SM_; Sk = SM_;
        Q = tq + (size_t)bh * SM_ * D_;
        K = tk + (size_t)bh * SM_ * D_;
        A = out + O_A2 + (size_t)bh * SM_ * SM_;
    } else {
        Sq = SM_; Sk = SM_;
        Q = dq + (size_t)bh * SM_ * D_;
        K = dk + (size_t)bh * SM_ * D_;
        A = out + O_A3 + (size_t)bh * SM_ * SM_;
    }

    const int q0  = blockIdx.y * 128;
    const int c0  = blockIdx.x * 128;
    const int tid = threadIdx.x;

    // Load tiles (d-major in smem). Consecutive threads take consecutive rows
    // so the 4 scalar smem stores per float4 are bank-conflict-free.
    #pragma unroll 4
    for (int i = tid; i < 128 * 16; i += 256) {
        int row = i & 127;
        int dv  = i >> 7;           // 0..15 -> d = dv*4
        float4 qv = make_float4(0.f, 0.f, 0.f, 0.f);
        float4 kv = make_float4(0.f, 0.f, 0.f, 0.f);
        if (q0 + row < Sq) qv = *(const float4*)(Q + (size_t)(q0 + row) * D_ + dv * 4);
        if (c0 + row < Sk) kv = *(const float4*)(K + (size_t)(c0 + row) * D_ + dv * 4);
        Qs[dv * 4 + 0][row] = qv.x; Qs[dv * 4 + 1][row] = qv.y;
        Qs[dv * 4 + 2][row] = qv.z; Qs[dv * 4 + 3][row] = qv.w;
        Ks[dv * 4 + 0][row] = kv.x; Ks[dv * 4 + 1][row] = kv.y;
        Ks[dv * 4 + 2][row] = kv.z; Ks[dv * 4 + 3][row] = kv.w;
    }
    __syncthreads();

    const int tx = tid & 15;
    const int ty = tid >> 4;

    float acc[8][8];
    #pragma unroll
    for (int i = 0; i < 8; ++i)
        #pragma unroll
        for (int j = 0; j < 8; ++j) acc[i][j] = 0.f;

    #pragma unroll 4
    for (int dd = 0; dd < 64; ++dd) {
        float4 a0 = *(const float4*)&Qs[dd][ty * 8];
        float4 a1 = *(const float4*)&Qs[dd][ty * 8 + 4];
        float4 b0 = *(const float4*)&Ks[dd][tx * 8];
        float4 b1 = *(const float4*)&Ks[dd][tx * 8 + 4];
        float qf[8] = {a0.x, a0.y, a0.z, a0.w, a1.x, a1.y, a1.z, a1.w};
        float kf[8] = {b0.x, b0.y, b0.z, b0.w, b1.x, b1.y, b1.z, b1.w};
        #pragma unroll
        for (int i = 0; i < 8; ++i)
            #pragma unroll
            for (int j = 0; j < 8; ++j)
                acc[i][j] = fmaf(qf[i], kf[j], acc[i][j]);
    }

    #pragma unroll
    for (int i = 0; i < 8; ++i) {
        int qq = q0 + ty * 8 + i;
        if (qq >= Sq) break;
        size_t rowbase = (size_t)qq * Sk;
        #pragma unroll
        for (int j = 0; j < 8; ++j) {
            int cc = c0 + tx * 8 + j;
            if (cc >= Sk) break;
            float s = acc[i][j] * INV_T;
            if (M && M[(size_t)qq * S_ + cc] == 0) s = neg_big();
            A[rowbase + cc] = s;
        }
    }
}

// ---------------------------------------------------------------------------
// Kernel B: in-place row softmax over the attn buffers.
// One block of 256 threads per row; row (<=2048 floats) cached in registers.
// ---------------------------------------------------------------------------
__global__ __launch_bounds__(256) void softmax_kernel(float* __restrict__ out)
{
    const int row    = blockIdx.x;
    const int z      = blockIdx.y;
    const int stream = z >> 4;
    const int bh     = z & 15;

    int Sk;
    float* A;
    if (stream == 0)      { Sk = S_;  A = out + O_A1 + (size_t)bh * S_  * S_;  }
    else if (stream == 1) { Sk = SM_; A = out + O_A2 + (size_t)bh * SM_ * SM_; }
    else                  { Sk = SM_; A = out + O_A3 + (size_t)bh * SM_ * SM_; }
    if (row >= Sk) return;                 // Sq == Sk for every stream

    float* r = A + (size_t)row * Sk;
    const int tid = threadIdx.x;

    float v[8];
    #pragma unroll
    for (int u = 0; u < 8; ++u) {
        int i = u * 256 + tid;
        v[u] = (i < Sk) ? r[i] : -3.0e38f;
    }

    // ---- block max ----
    float m = v[0];
    #pragma unroll
    for (int u = 1; u < 8; ++u) m = fmaxf(m, v[u]);
    #pragma unroll
    for (int o = 16; o > 0; o >>= 1) m = fmaxf(m, __shfl_xor_sync(0xffffffffu, m, o));

    __shared__ float sm[8];
    const int w = tid >> 5, l = tid & 31;
    if (l == 0) sm[w] = m;
    __syncthreads();
    if (tid < 32) {
        float t = (tid < 8) ? sm[tid] : -3.0e38f;
        #pragma unroll
        for (int o = 4; o > 0; o >>= 1) t = fmaxf(t, __shfl_xor_sync(0xffffffffu, t, o));
        if (tid == 0) sm[0] = t;
    }
    __syncthreads();
    m = sm[0];
    __syncthreads();

    // ---- exp + block sum ----
    float s = 0.f;
    #pragma unroll
    for (int u = 0; u < 8; ++u) {
        v[u] = __expf(v[u] - m);           // padded lanes -> exp(-inf) = 0
        s += v[u];
    }
    #pragma unroll
    for (int o = 16; o > 0; o >>= 1) s += __shfl_xor_sync(0xffffffffu, s, o);
    if (l == 0) sm[w] = s;
    __syncthreads();
    if (tid < 32) {
        float t = (tid < 8) ? sm[tid] : 0.f;
        #pragma unroll
        for (int o = 4; o > 0; o >>= 1) t += __shfl_xor_sync(0xffffffffu, t, o);
        if (tid == 0) sm[0] = t;
    }
    __syncthreads();
    const float inv = 1.0f / sm[0];

    #pragma unroll
    for (int u = 0; u < 8; ++u) {
        int i = u * 256 + tid;
        if (i < Sk) r[i] = v[u] * inv;
    }
}

// ---------------------------------------------------------------------------
// Kernel C: O = P @ V  (optionally P+P2, optionally accumulated into O).
// 256 rows x 64 cols per block, K-chunks of 32, 256 threads, 8x8 micro-tile.
// jobs: 0 attn1@poi_v -> poi_out (store)
//       1 attn2@time_v -> time_out (store)
//       2 attn3@dist_v -> dist_out (store)
//       3 (attn2+attn3)@poi_v[:-1] -> poi_out[1:] (accumulate)
// ---------------------------------------------------------------------------
__global__ __launch_bounds__(256) void pv_kernel(
    const float* __restrict__ pv, const float* __restrict__ tv,
    const float* __restrict__ dvv, float* __restrict__ out, int job_base)
{
    __shared__ float Ps[256][33];
    __shared__ __align__(16) float Vs[32][68];

    const int z   = blockIdx.z;
    const int job = job_base + (z >> 4);
    const int bh  = z & 15;

    const float *P, *P2 = nullptr, *V;
    float* O;
    int Sq, Sk;
    bool accum = false;

    if (job == 0) {
        Sq = S_; Sk = S_;
        P = out + O_A1 + (size_t)bh * S_ * S_;
        V = pv + (size_t)bh * S_ * D_;
        O = out + O_POI + (size_t)bh * S_ * D_;
    } else if (job == 1) {
        Sq = SM_; Sk = SM_;
        P = out + O_A2 + (size_t)bh * SM_ * SM_;
        V = tv + (size_t)bh * SM_ * D_;
        O = out + O_TIME + (size_t)bh * SM_ * D_;
    } else if (job == 2) {
        Sq = SM_; Sk = SM_;
        P = out + O_A3 + (size_t)bh * SM_ * SM_;
        V = dvv + (size_t)bh * SM_ * D_;
        O = out + O_DIST + (size_t)bh * SM_ * D_;
    } else {
        Sq = SM_; Sk = SM_;
        P  = out + O_A2 + (size_t)bh * SM_ * SM_;
        P2 = out + O_A3 + (size_t)bh * SM_ * SM_;
        V  = pv + (size_t)bh * S_ * D_;             // rows 0..2046 = poi_v[:-1]
        O  = out + O_POI + (size_t)bh * S_ * D_ + D_;  // shifted by one row
        accum = true;
    }

    const int r0   = blockIdx.x * 256;
    const int tid  = threadIdx.x;
    const int rowt = tid >> 3;       // 0..31 -> 8 rows each
    const int colt = tid & 7;        // 0..7  -> 8 cols each

    float acc[8][8];
    #pragma unroll
    for (int i = 0; i < 8; ++i)
        #pragma unroll
        for (int j = 0; j < 8; ++j) acc[i][j] = 0.f;

    for (int ck = 0; ck < Sk; ck += 32) {
        // load P chunk (coalesced along k), optional P2 add
        #pragma unroll 8
        for (int it = 0; it < 32; ++it) {
            int i  = it * 256 + tid;
            int kk = i & 31, rr = i >> 5;
            int gr = r0 + rr, gk = ck + kk;
            float p = 0.f;
            if (gr < Sq && gk < Sk) {
                size_t idx = (size_t)gr * Sk + gk;
                p = P[idx];
                if (P2) p += P2[idx];
            }
            Ps[rr][kk] = p;
        }
        // load V chunk (coalesced along d)
        #pragma unroll
        for (int it = 0; it < 8; ++it) {
            int i  = it * 256 + tid;
            int dd = i & 63, kk = i >> 6;
            int gk = ck + kk;
            Vs[kk][dd] = (gk < Sk) ? V[(size_t)gk * D_ + dd] : 0.f;
        }
        __syncthreads();

        #pragma unroll 4
        for (int kk = 0; kk < 32; ++kk) {
            float pf[8];
            #pragma unroll
            for (int i = 0; i < 8; ++i) pf[i] = Ps[rowt * 8 + i][kk];
            float4 v0 = *(const float4*)&Vs[kk][colt * 8];
            float4 v1 = *(const float4*)&Vs[kk][colt * 8 + 4];
            float vf[8] = {v0.x, v0.y, v0.z, v0.w, v1.x, v1.y, v1.z, v1.w};
            #pragma unroll
            for (int i = 0; i < 8; ++i)
                #pragma unroll
                for (int j = 0; j < 8; ++j)
                    acc[i][j] = fmaf(pf[i], vf[j], acc[i][j]);
        }
        __syncthreads();
    }

    #pragma unroll
    for (int i = 0; i < 8; ++i) {
        int gr = r0 + rowt * 8 + i;
        if (gr >= Sq) break;
        size_t base = (size_t)gr * D_ + colt * 8;
        if (accum) {
            #pragma unroll
            for (int j = 0; j < 8; ++j) O[base + j] += acc[i][j];
        } else {
            #pragma unroll
            for (int j = 0; j < 8; ++j) O[base + j] = acc[i][j];
        }
    }
}

// ---------------------------------------------------------------------------
extern "C" void kernel_launch(void* const* d_in, const int* in_sizes, int n_in,
                              void* d_out, int out_size)
{
    const float* pq  = (const float*)d_in[0];
    const float* pk  = (const float*)d_in[1];
    const float* pv  = (const float*)d_in[2];
    const float* tq  = (const float*)d_in[3];
    const float* tk  = (const float*)d_in[4];
    const float* tv  = (const float*)d_in[5];
    const float* dq  = (const float*)d_in[6];
    const float* dk  = (const float*)d_in[7];
    const float* dvv = (const float*)d_in[8];
    const int*   msk = (const int*)d_in[9];
    float* out = (float*)d_out;

    // A: scores (+ mask for stream 0)
    scores_kernel<<<dim3(16, 16, 48), 256>>>(pq, pk, tq, tk, dq, dk, msk, out);
    // B: row softmax, in place in the attn output buffers
    softmax_kernel<<<dim3(2048, 48), 256>>>(out);
    // C: direct P@V outputs (jobs 0..2)
    pv_kernel<<<dim3(8, 1, 48), 256>>>(pv, tv, dvv, out, 0);
    // C: cross term (job 3), must come after job 0's store (stream-ordered)
    pv_kernel<<<dim3(8, 1, 16), 256>>>(pv, tv, dvv, out, 3);
}

// round 2
// speedup vs baseline: 1.0082x; 1.0082x over previous
#include <cuda_runtime.h>

// Problem constants (B=2, H=8, S=2048, Sm=2047, D=64)
#define B_   2
#define H_   8
#define S_   2048
#define SM_  2047
#define D_   64
#define BH_  16          // B*H

__device__ __forceinline__ float neg_big() { return -1e9f; }
#define INV_T 0.125f     // 1/TEMPERATURE (= 1/8)

// Output layout (floats), tuple order:
// poi_output, time_output, distance_output, attn1, attn2, attn3
#define O_POI   ((size_t)0)
#define O_TIME  ((size_t)2097152)     // + 16*2048*64
#define O_DIST  ((size_t)4193280)     // + 16*2047*64
#define O_A1    ((size_t)6289408)     // + 16*2047*64
#define O_A2    ((size_t)73398272)    // + 16*2048*2048
#define O_A3    ((size_t)140441616)   // + 16*2047*2047

// ---------------------------------------------------------------------------
// Kernel A: masked scaled scores  S = (Q @ K^T) / T  (mask on stream 0)
// 128x128 output tile per block, 256 threads, 8x8 micro-tile, D=64 fully
// resident in shared memory (stored d-major for conflict-free vector reads).
// ---------------------------------------------------------------------------
__global__ __launch_bounds__(256) void scores_kernel(
    const float* __restrict__ pq, const float* __restrict__ pk,
    const float* __restrict__ tq, const float* __restrict__ tk,
    const float* __restrict__ dq, const float* __restrict__ dk,
    const int*   __restrict__ mask, float* __restrict__ out)
{
    __shared__ __align__(16) float Qs[64][132];
    __shared__ __align__(16) float Ks[64][132];

    const int z      = blockIdx.z;
    const int stream = z >> 4;
    const int bh     = z & 15;

    const float *Q, *K;
    float* A;
    int Sq, Sk;
    const int* M = nullptr;

    if (stream == 0) {
        Sq = S_; Sk = S_;
        Q = pq + (size_t)bh * S_ * D_;
        K = pk + (size_t)bh * S_ * D_;
        A = out + O_A1 + (size_t)bh * S_ * S_;
        M = mask + (size_t)(bh >> 3) * S_ * S_;   // b = bh / H
    } else if (stream == 1) {
        Sq = SM_; Sk = SM_;
        Q = tq + (size_t)bh * SM_ * D_;
        K = tk + (size_t)bh * SM_ * D_;
        A = out + O_A2 + (size_t)bh * SM_ * SM_;
    } else {
        Sq = SM_; Sk = SM_;
        Q = dq + (size_t)bh * SM_ * D_;
        K = dk + (size_t)bh * SM_ * D_;
        A = out + O_A3 + (size_t)bh * SM_ * SM_;
    }

    const int q0  = blockIdx.y * 128;
    const int c0  = blockIdx.x * 128;
    const int tid = threadIdx.x;

    // Load tiles (d-major in smem). Consecutive threads take consecutive rows
    // so the 4 scalar smem stores per float4 are bank-conflict-free.
    #pragma unroll 4
    for (int i = tid; i < 128 * 16; i += 256) {
        int row = i & 127;
        int dv  = i >> 7;           // 0..15 -> d = dv*4
        float4 qv = make_float4(0.f, 0.f, 0.f, 0.f);
        float4 kv = make_float4(0.f, 0.f, 0.f, 0.f);
        if (q0 + row < Sq) qv = *(const float4*)(Q + (size_t)(q0 + row) * D_ + dv * 4);
        if (c0 + row < Sk) kv = *(const float4*)(K + (size_t)(c0 + row) * D_ + dv * 4);
        Qs[dv * 4 + 0][row] = qv.x; Qs[dv * 4 + 1][row] = qv.y;
        Qs[dv * 4 + 2][row] = qv.z; Qs[dv * 4 + 3][row] = qv.w;
        Ks[dv * 4 + 0][row] = kv.x; Ks[dv * 4 + 1][row] = kv.y;
        Ks[dv * 4 + 2][row] = kv.z; Ks[dv * 4 + 3][row] = kv.w;
    }
    __syncthreads();

    const int tx = tid & 15;
    const int ty = tid >> 4;

    float acc[8][8];
    #pragma unroll
    for (int i = 0; i < 8; ++i)
        #pragma unroll
        for (int j = 0; j < 8; ++j) acc[i][j] = 0.f;

    #pragma unroll 4
    for (int dd = 0; dd < 64; ++dd) {
        float4 a0 = *(const float4*)&Qs[dd][ty * 8];
        float4 a1 = *(const float4*)&Qs[dd][ty * 8 + 4];
        float4 b0 = *(const float4*)&Ks[dd][tx * 8];
        float4 b1 = *(const float4*)&Ks[dd][tx * 8 + 4];
        float qf[8] = {a0.x, a0.y, a0.z, a0.w, a1.x, a1.y, a1.z, a1.w};
        float kf[8] = {b0.x, b0.y, b0.z, b0.w, b1.x, b1.y, b1.z, b1.w};
        #pragma unroll
        for (int i = 0; i < 8; ++i)
            #pragma unroll
            for (int j = 0; j < 8; ++j)
                acc[i][j] = fmaf(qf[i], kf[j], acc[i][j]);
    }

    #pragma unroll
    for (int i = 0; i < 8; ++i) {
        int qq = q0 + ty * 8 + i;
        if (qq >= Sq) break;
        size_t rowbase = (size_t)qq * Sk;
        #pragma unroll
        for (int j = 0; j < 8; ++j) {
            int cc = c0 + tx * 8 + j;
            if (cc >= Sk) break;
            float s = acc[i][j] * INV_T;
            if (M && M[(size_t)qq * S_ + cc] == 0) s = neg_big();
            A[rowbase + cc] = s;
        }
    }
}

// ---------------------------------------------------------------------------
// Kernel B: in-place row softmax over the attn buffers.
// One block of 256 threads per row; row (<=2048 floats) cached in registers.
// ---------------------------------------------------------------------------
__global__ __launch_bounds__(256) void softmax_kernel(float* __restrict__ out)
{
    const int row    = blockIdx.x;
    const int z      = blockIdx.y;
    const int stream = z >> 4;
    const int bh     = z & 15;

    int Sk;
    float* A;
    if (stream == 0)      { Sk = S_;  A = out + O_A1 + (size_t)bh * S_  * S_;  }
    else if (stream == 1) { Sk = SM_; A = out + O_A2 + (size_t)bh * SM_ * SM_; }
    else                  { Sk = SM_; A = out + O_A3 + (size_t)bh * SM_ * SM_; }
    if (row >= Sk) return;                 // Sq == Sk for every stream

    float* r = A + (size_t)row * Sk;
    const int tid = threadIdx.x;

    float v[8];
    #pragma unroll
    for (int u = 0; u < 8; ++u) {
        int i = u * 256 + tid;
        v[u] = (i < Sk) ? r[i] : -3.0e38f;
    }

    // ---- block max ----
    float m = v[0];
    #pragma unroll
    for (int u = 1; u < 8; ++u) m = fmaxf(m, v[u]);
    #pragma unroll
    for (int o = 16; o > 0; o >>= 1) m = fmaxf(m, __shfl_xor_sync(0xffffffffu, m, o));

    __shared__ float sm[8];
    const int w = tid >> 5, l = tid & 31;
    if (l == 0) sm[w] = m;
    __syncthreads();
    if (tid < 32) {
        float t = (tid < 8) ? sm[tid] : -3.0e38f;
        #pragma unroll
        for (int o = 4; o > 0; o >>= 1) t = fmaxf(t, __shfl_xor_sync(0xffffffffu, t, o));
        if (tid == 0) sm[0] = t;
    }
    __syncthreads();
    m = sm[0];
    __syncthreads();

    // ---- exp + block sum ----
    float s = 0.f;
    #pragma unroll
    for (int u = 0; u < 8; ++u) {
        v[u] = __expf(v[u] - m);           // padded lanes -> exp(-inf) = 0
        s += v[u];
    }
    #pragma unroll
    for (int o = 16; o > 0; o >>= 1) s += __shfl_xor_sync(0xffffffffu, s, o);
    if (l == 0) sm[w] = s;
    __syncthreads();
    if (tid < 32) {
        float t = (tid < 8) ? sm[tid] : 0.f;
        #pragma unroll
        for (int o = 4; o > 0; o >>= 1) t += __shfl_xor_sync(0xffffffffu, t, o);
        if (tid == 0) sm[0] = t;
    }
    __syncthreads();
    const float inv = 1.0f / sm[0];

    #pragma unroll
    for (int u = 0; u < 8; ++u) {
        int i = u * 256 + tid;
        if (i < Sk) r[i] = v[u] * inv;
    }
}

// ---------------------------------------------------------------------------
// Kernel C: O = P @ V  (optionally P+P2, optionally accumulated into O).
// 256 rows x 64 cols per block, K-chunks of 32, 256 threads, 8x8 micro-tile.
// jobs: 0 attn1@poi_v -> poi_out (store)
//       1 attn2@time_v -> time_out (store)
//       2 attn3@dist_v -> dist_out (store)
//       3 (attn2+attn3)@poi_v[:-1] -> poi_out[1:] (accumulate)
// ---------------------------------------------------------------------------
__global__ __launch_bounds__(256) void pv_kernel(
    const float* __restrict__ pv, const float* __restrict__ tv,
    const float* __restrict__ dvv, float* __restrict__ out, int job_base)
{
    __shared__ float Ps[256][33];
    __shared__ __align__(16) float Vs[32][68];

    const int z   = blockIdx.z;
    const int job = job_base + (z >> 4);
    const int bh  = z & 15;

    const float *P, *P2 = nullptr, *V;
    float* O;
    int Sq, Sk;
    bool accum = false;

    if (job == 0) {
        Sq = S_; Sk = S_;
        P = out + O_A1 + (size_t)bh * S_ * S_;
        V = pv + (size_t)bh * S_ * D_;
        O = out + O_POI + (size_t)bh * S_ * D_;
    } else if (job == 1) {
        Sq = SM_; Sk = SM_;
        P = out + O_A2 + (size_t)bh * SM_ * SM_;
        V = tv + (size_t)bh * SM_ * D_;
        O = out + O_TIME + (size_t)bh * SM_ * D_;
    } else if (job == 2) {
        Sq = SM_; Sk = SM_;
        P = out + O_A3 + (size_t)bh * SM_ * SM_;
        V = dvv + (size_t)bh * SM_ * D_;
        O = out + O_DIST + (size_t)bh * SM_ * D_;
    } else {
        Sq = SM_; Sk = SM_;
        P  = out + O_A2 + (size_t)bh * SM_ * SM_;
        P2 = out + O_A3 + (size_t)bh * SM_ * SM_;
        V  = pv + (size_t)bh * S_ * D_;             // rows 0..2046 = poi_v[:-1]
        O  = out + O_POI + (size_t)bh * S_ * D_ + D_;  // shifted by one row
        accum = true;
    }

    const int r0   = blockIdx.x * 256;
    const int tid  = threadIdx.x;
    const int rowt = tid >> 3;       // 0..31 -> 8 rows each
    const int colt = tid & 7;        // 0..7  -> 8 cols each

    float acc[8][8];
    #pragma unroll
    for (int i = 0; i < 8; ++i)
        #pragma unroll
        for (int j = 0; j < 8; ++j) acc[i][j] = 0.f;

    for (int ck = 0; ck < Sk; ck += 32) {
        // load P chunk (coalesced along k), optional P2 add
        #pragma unroll 8
        for (int it = 0; it < 32; ++it) {
            int i  = it * 256 + tid;
            int kk = i & 31, rr = i >> 5;
            int gr = r0 + rr, gk = ck + kk;
            float p = 0.f;
            if (gr < Sq && gk < Sk) {
                size_t idx = (size_t)gr * Sk + gk;
                p = P[idx];
                if (P2) p += P2[idx];
            }
            Ps[rr][kk] = p;
        }
        // load V chunk (coalesced along d)
        #pragma unroll
        for (int it = 0; it < 8; ++it) {
            int i  = it * 256 + tid;
            int dd = i & 63, kk = i >> 6;
            int gk = ck + kk;
            Vs[kk][dd] = (gk < Sk) ? V[(size_t)gk * D_ + dd] : 0.f;
        }
        __syncthreads();

        #pragma unroll 4
        for (int kk = 0; kk < 32; ++kk) {
            float pf[8];
            #pragma unroll
            for (int i = 0; i < 8; ++i) pf[i] = Ps[rowt * 8 + i][kk];
            float4 v0 = *(const float4*)&Vs[kk][colt * 8];
            float4 v1 = *(const float4*)&Vs[kk][colt * 8 + 4];
            float vf[8] = {v0.x, v0.y, v0.z, v0.w, v1.x, v1.y, v1.z, v1.w};
            #pragma unroll
            for (int i = 0; i < 8; ++i)
                #pragma unroll
                for (int j = 0; j < 8; ++j)
                    acc[i][j] = fmaf(pf[i], vf[j], acc[i][j]);
        }
        __syncthreads();
    }

    #pragma unroll
    for (int i = 0; i < 8; ++i) {
        int gr = r0 + rowt * 8 + i;
        if (gr >= Sq) break;
        size_t base = (size_t)gr * D_ + colt * 8;
        if (accum) {
            #pragma unroll
            for (int j = 0; j < 8; ++j) O[base + j] += acc[i][j];
        } else {
            #pragma unroll
            for (int j = 0; j < 8; ++j) O[base + j] = acc[i][j];
        }
    }
}

// ---------------------------------------------------------------------------
extern "C" void kernel_launch(void* const* d_in, const int* in_sizes, int n_in,
                              void* d_out, int out_size)
{
    const float* pq  = (const float*)d_in[0];
    const float* pk  = (const float*)d_in[1];
    const float* pv  = (const float*)d_in[2];
    const float* tq  = (const float*)d_in[3];
    const float* tk  = (const float*)d_in[4];
    const float* tv  = (const float*)d_in[5];
    const float* dq  = (const float*)d_in[6];
    const float* dk  = (const float*)d_in[7];
    const float* dvv = (const float*)d_in[8];
    const int*   msk = (const int*)d_in[9];
    float* out = (float*)d_out;

    // A: scores (+ mask for stream 0)
    scores_kernel<<<dim3(16, 16, 48), 256>>>(pq, pk, tq, tk, dq, dk, msk, out);
    // B: row softmax, in place in the attn output buffers
    softmax_kernel<<<dim3(2048, 48), 256>>>(out);
    // C: direct P@V outputs (jobs 0..2)
    pv_kernel<<<dim3(8, 1, 48), 256>>>(pv, tv, dvv, out, 0);
    // C: cross term (job 3), must come after job 0's store (stream-ordered)
    pv_kernel<<<dim3(8, 1, 16), 256>>>(pv, tv, dvv, out, 3);
}